// round 13
// baseline (speedup 1.0000x reference)
#include <cuda_runtime.h>
#include <cstdint>

#define BSZ 256
#define TLEN 512
#define KTAG 48
#define KK 2304                 // floats per (b,t) tile
#define PAD 72                  // padded row stride; (8y+j) bank map -> conflict-free
#define TILE_F (KTAG*PAD)       // 3456 floats per padded tile
#define START_TAG 46
#define END_TAG 47
#define NTHREADS 192
#define NM 12                   // rows per thread: y + 4m, m = 0..11
#define NBUF 8
#define CPR 12                  // 16B chunks per tile row (48 floats = 192B)
#define PFD 64                  // L2 prefetch distance (tiles) for long chains
#define LONG_LEN 320            // chains at least this long get L2 priority
#define L2E 1.44269504088896f
#define LN2 0.6931471805599453f

__device__ float g_partial[BSZ];
__device__ unsigned int g_count;   // zero-init; reset by reducing CTA

__device__ __forceinline__ void cp16(uint32_t dst_smem, const void* src) {
    asm volatile("cp.async.cg.shared.global [%0], [%1], 16;" :: "r"(dst_smem), "l"(src));
}
__device__ __forceinline__ void cp_commit() {
    asm volatile("cp.async.commit_group;" ::: "memory");
}
template<int N>
__device__ __forceinline__ void cp_wait() {
    asm volatile("cp.async.wait_group %0;" :: "n"(N) : "memory");
}
__device__ __forceinline__ void l2_prefetch(const void* p) {
    asm volatile("prefetch.global.L2 [%0];" :: "l"(p));
}
__device__ __forceinline__ float fast_ex2(float x) {
    float r; asm("ex2.approx.ftz.f32 %0, %1;" : "=f"(r) : "f"(x)); return r;
}
__device__ __forceinline__ float fast_lg2(float x) {
    float r; asm("lg2.approx.ftz.f32 %0, %1;" : "=f"(r) : "f"(x)); return r;
}
__device__ __forceinline__ float fast_rcp(float x) {
    float r; asm("rcp.approx.ftz.f32 %0, %1;" : "=f"(r) : "f"(x)); return r;
}

// One step for tile T. P = T&1; SCUR=T&7, SNXT=(T+1)&7, SPRE=(T+5)&7.
// srcp -> tile T+5 on entry (prologue loaded 0..5); cp_wait<4> completes <= T+2.
// pfp -> this thread's 128B line of tile T+PFD (long chains only).
#define STEP(T, P, SCUR, SNXT, SPRE)                                             \
  {                                                                              \
    __syncthreads();                                /* eag_T published */        \
    const float* eg = eagm + (P) * KTAG;                                         \
    const float e0v = eg[0];                                                     \
    const float rc  = fast_rcp(e0v);                                             \
    const float lgv = fast_lg2(e0v);                                             \
    float a0 = esc[0] * eg[y +  0], a1 = esc[1] * eg[y +  4];                    \
    float a2 = esc[2] * eg[y +  8], a3 = esc[3] * eg[y + 12];                    \
    a0 = fmaf(esc[4],  eg[y + 16], a0); a1 = fmaf(esc[5],  eg[y + 20], a1);      \
    a2 = fmaf(esc[6],  eg[y + 24], a2); a3 = fmaf(esc[7],  eg[y + 28], a3);      \
    a0 = fmaf(esc[8],  eg[y + 32], a0); a1 = fmaf(esc[9],  eg[y + 36], a1);      \
    a2 = fmaf(esc[10], eg[y + 40], a2); a3 = fmaf(esc[11], eg[y + 44], a3);      \
    float sdot = (a0 + a1) + (a2 + a3);                                          \
    if ((T) + 5 < len) {                            /* prefetch tile T+5 */      \
      uint32_t d = sbase + (uint32_t)(SPRE) * (TILE_F * 4);                      \
      cp16(d + d0, srcp + s0); cp16(d + d1, srcp + s1); cp16(d + d2, srcp + s2); \
    }                                                                            \
    srcp += KK * 4;                                                              \
    if (longp && (T) + PFD < len) l2_prefetch(pfp);  /* bank DRAM share */       \
    pfp += KK * 4;                                                               \
    cp_commit();                                                                 \
    cp_wait<4>();                                   /* tiles <= T+2 complete */  \
    if ((T) + 1 < len) {                            /* esc <- exps(tile T+1) */  \
      const float* rp = buf + (SNXT) * TILE_F + ro;                              \
      _Pragma("unroll")                                                          \
      for (int m = 0; m < NM; ++m) esc[m] = fast_ex2(rp[m * 4 * PAD] * L2E);     \
    }                                                                            \
    if (tid == 0) {                                 /* Kahan true_sum += */      \
      float yk = buf[(SCUR) * TILE_F + tgt_s[T]] - tc;                           \
      float tk = true_sum + yk;                                                  \
      tc = (tk - true_sum) - yk;                                                 \
      true_sum = tk;                                                             \
    }                                                                            \
    sdot += __shfl_xor_sync(0xffffffffu, sdot, 1);                               \
    sdot += __shfl_xor_sync(0xffffffffu, sdot, 2);                               \
    if (y == 0) eagm[((P) ^ 1) * KTAG + j] = sdot * rc;                          \
    { float yk = lgv - Nc;                          /* Kahan N += lgv */         \
      float tk = N + yk;                                                         \
      Nc = (tk - N) - yk;                                                        \
      N = tk; }                                                                  \
  }

__global__ __launch_bounds__(NTHREADS, 2)
void crf_fwd_kernel(const float* __restrict__ scores,
                    const int* __restrict__ targets,
                    const int* __restrict__ lengths,
                    float* __restrict__ out)
{
    extern __shared__ float sdyn[];
    float* buf   = sdyn;                          // NBUF * TILE_F
    float* eagm  = buf + NBUF * TILE_F;           // 2 * KTAG
    int*   tgt_s = (int*)(eagm + 2 * KTAG);       // TLEN

    const int bid = blockIdx.x;
    // pair batch s with 255-s (lengths sorted desc) for per-SM balance
    const int b = (bid < 148) ? bid : (403 - bid);

    const int tid = threadIdx.x;
    const int j   = tid >> 2;            // column 0..47
    const int y   = tid & 3;             // row-group 0..3 (rows y+4m)
    const int len = lengths[b];

    const float* base = scores + (size_t)b * TLEN * KK;

    for (int t = tid; t < len; t += NTHREADS) {
        int tg = targets[b * TLEN + t];
        tgt_s[t] = (tg / KTAG) * PAD + (tg % KTAG);
    }

    // cp.async: exactly 3 chunks per thread (576 = 3*192)
    const uint32_t sbase = (uint32_t)__cvta_generic_to_shared(buf);
    const int c0 = tid, c1 = tid + NTHREADS, c2 = tid + 2 * NTHREADS;
    const uint32_t d0 = (uint32_t)((c0 / CPR) * (PAD * 4) + (c0 % CPR) * 16);
    const uint32_t d1 = (uint32_t)((c1 / CPR) * (PAD * 4) + (c1 % CPR) * 16);
    const uint32_t d2 = (uint32_t)((c2 / CPR) * (PAD * 4) + (c2 % CPR) * 16);
    const uint32_t s0 = (uint32_t)c0 * 16, s1 = (uint32_t)c1 * 16, s2 = (uint32_t)c2 * 16;
    const int ro = y * PAD + j;          // rows y+4m at +m*4*PAD

    // L2 priority prefetch: 72 threads cover one 9216B tile in 128B lines
    const bool longp = (tid < 72) && (len >= LONG_LEN);
    const char* pfp = (const char*)base + (size_t)(1 + PFD) * (KK * 4) + tid * 128;

    // prologue: prime tiles 0..5 into slots 0..5 (6 commits)
    #pragma unroll
    for (int k = 0; k < 6; ++k) {
        if (k < len) {
            const char* s = (const char*)(base + (size_t)k * KK);
            uint32_t d = sbase + (uint32_t)k * (TILE_F * 4);
            cp16(d + d0, s + s0); cp16(d + d1, s + s1); cp16(d + d2, s + s2);
        }
        cp_commit();
    }
    cp_wait<4>();            // tiles 0,1 complete
    __syncthreads();         // published

    // eag_1 at parity 1
    if (y == 0)
        eagm[KTAG + j] = fast_ex2(buf[START_TAG * PAD + j] * L2E);

    float esc[NM];
    if (len > 1) {
        const float* rp = buf + 1 * TILE_F + ro;       // tile 1
        #pragma unroll
        for (int m = 0; m < NM; ++m) esc[m] = fast_ex2(rp[m * 4 * PAD] * L2E);
    }
    float true_sum = (tid == 0) ? buf[tgt_s[0]] : 0.0f;
    float tc = 0.0f, N = 0.0f, Nc = 0.0f;
    const char* srcp = (const char*)(base + (size_t)6 * KK);   // tile 6 = (t=1)+5

    int t = 1;
    for (; t + 7 < len; t += 8) {        // t ≡ 1 (mod 8): compile-time slots
        STEP(t,     1, 1, 2, 6)
        STEP(t + 1, 0, 2, 3, 7)
        STEP(t + 2, 1, 3, 4, 0)
        STEP(t + 3, 0, 4, 5, 1)
        STEP(t + 4, 1, 5, 6, 2)
        STEP(t + 5, 0, 6, 7, 3)
        STEP(t + 6, 1, 7, 0, 4)
        STEP(t + 7, 0, 0, 1, 5)
    }
    for (; t < len; ++t) {               // remainder (<=7): runtime slots
        STEP(t, (t & 1), (t & 7), ((t + 1) & 7), ((t + 5) & 7))
    }

    __syncthreads();
    if (tid == 0)
        g_partial[b] = (fast_lg2(eagm[(len & 1) * KTAG + END_TAG]) + N) * LN2 - true_sum;

    // last-arriving CTA reduces (deterministic fixed-order tree)
    if (tid < 32) {
        unsigned done = 0;
        if (tid == 0) {
            __threadfence();
            done = atomicAdd(&g_count, 1u);
        }
        done = __shfl_sync(0xffffffffu, done, 0);
        if (done == BSZ - 1) {
            __threadfence();
            const volatile float* gp = g_partial;
            float s = 0.0f;
            #pragma unroll
            for (int k = 0; k < BSZ / 32; ++k) s += gp[tid + 32 * k];
            s += __shfl_xor_sync(0xffffffffu, s, 16);
            s += __shfl_xor_sync(0xffffffffu, s, 8);
            s += __shfl_xor_sync(0xffffffffu, s, 4);
            s += __shfl_xor_sync(0xffffffffu, s, 2);
            s += __shfl_xor_sync(0xffffffffu, s, 1);
            if (tid == 0) {
                out[0] = s / (float)BSZ;
                g_count = 0;             // reset for next graph replay
            }
        }
    }
}

extern "C" void kernel_launch(void* const* d_in, const int* in_sizes, int n_in,
                              void* d_out, int out_size)
{
    const float* scores  = (const float*)d_in[0];
    const int*   targets = (const int*)d_in[1];
    const int*   lengths = (const int*)d_in[2];
    float* out = (float*)d_out;

    const int smem_bytes = (NBUF * TILE_F + 2 * KTAG) * 4 + TLEN * 4;  // ~110.4 KB
    cudaFuncSetAttribute(crf_fwd_kernel,
                         cudaFuncAttributeMaxDynamicSharedMemorySize, smem_bytes);

    crf_fwd_kernel<<<BSZ, NTHREADS, smem_bytes>>>(scores, targets, lengths, out);
}

// round 14
// speedup vs baseline: 1.3393x; 1.3393x over previous
#include <cuda_runtime.h>
#include <cstdint>

#define BSZ 256
#define TLEN 512
#define KTAG 48
#define KK 2304                 // floats per (b,t) tile
#define PAD 72                  // padded row stride; (8y+j) bank map -> conflict-free
#define TILE_F (KTAG*PAD)       // 3456 floats per padded tile
#define START_TAG 46
#define END_TAG 47
#define NTHREADS 192
#define NM 12                   // rows per thread: y + 4m, m = 0..11
#define NBUF 8
#define CPR 12                  // 16B chunks per tile row (48 floats = 192B)
#define L2E 1.44269504088896f
#define LN2 0.6931471805599453f

__device__ float g_partial[BSZ];
__device__ unsigned int g_count;   // zero-init; reset by reducing CTA

__device__ __forceinline__ void cp16(uint32_t dst_smem, const void* src) {
    asm volatile("cp.async.cg.shared.global [%0], [%1], 16;" :: "r"(dst_smem), "l"(src));
}
__device__ __forceinline__ void cp_commit() {
    asm volatile("cp.async.commit_group;" ::: "memory");
}
template<int N>
__device__ __forceinline__ void cp_wait() {
    asm volatile("cp.async.wait_group %0;" :: "n"(N) : "memory");
}
__device__ __forceinline__ float fast_ex2(float x) {
    float r; asm("ex2.approx.ftz.f32 %0, %1;" : "=f"(r) : "f"(x)); return r;
}
__device__ __forceinline__ float fast_lg2(float x) {
    float r; asm("lg2.approx.ftz.f32 %0, %1;" : "=f"(r) : "f"(x)); return r;
}
__device__ __forceinline__ float fast_rcp(float x) {
    float r; asm("rcp.approx.ftz.f32 %0, %1;" : "=f"(r) : "f"(x)); return r;
}

// One step for tile T. P = T&1; SCUR=T&7, SNXT=(T+1)&7, SPRE=(T+6)&7.
// srcp -> tile T+6 on entry (prologue loaded 0..6). cp_wait<5> completes
// tiles <= T+1 (pending: T+2..T+6). Ring safety: write slot (T+6)&7 =
// (T-2)&7; tile T-2's last read preceded the STEP(T-1) barrier.
#define STEP(T, P, SCUR, SNXT, SPRE)                                             \
  {                                                                              \
    __syncthreads();                                /* eag_T published */        \
    const float* eg = eagm + (P) * KTAG;                                         \
    const float e0v = eg[0];                                                     \
    const float rc  = fast_rcp(e0v);                                             \
    const float lgv = fast_lg2(e0v);                                             \
    float a0 = esc[0] * eg[y +  0], a1 = esc[1] * eg[y +  4];                    \
    float a2 = esc[2] * eg[y +  8], a3 = esc[3] * eg[y + 12];                    \
    a0 = fmaf(esc[4],  eg[y + 16], a0); a1 = fmaf(esc[5],  eg[y + 20], a1);      \
    a2 = fmaf(esc[6],  eg[y + 24], a2); a3 = fmaf(esc[7],  eg[y + 28], a3);      \
    a0 = fmaf(esc[8],  eg[y + 32], a0); a1 = fmaf(esc[9],  eg[y + 36], a1);      \
    a2 = fmaf(esc[10], eg[y + 40], a2); a3 = fmaf(esc[11], eg[y + 44], a3);      \
    float sdot = (a0 + a1) + (a2 + a3);                                          \
    if ((T) + 6 < len) {                            /* prefetch tile T+6 */      \
      uint32_t d = sbase + (uint32_t)(SPRE) * (TILE_F * 4);                      \
      cp16(d + d0, srcp + s0); cp16(d + d1, srcp + s1); cp16(d + d2, srcp + s2); \
    }                                                                            \
    srcp += KK * 4;                                                              \
    cp_commit();                                                                 \
    cp_wait<5>();                                   /* tiles <= T+1 complete */  \
    if ((T) + 1 < len) {                            /* esc <- exps(tile T+1) */  \
      const float* rp = buf + (SNXT) * TILE_F + ro;                              \
      _Pragma("unroll")                                                          \
      for (int m = 0; m < NM; ++m) esc[m] = fast_ex2(rp[m * 4 * PAD] * L2E);     \
    }                                                                            \
    if (tid == 0) {                                 /* Kahan true_sum += */      \
      float yk = buf[(SCUR) * TILE_F + tgt_s[T]] - tc;                           \
      float tk = true_sum + yk;                                                  \
      tc = (tk - true_sum) - yk;                                                 \
      true_sum = tk;                                                             \
    }                                                                            \
    sdot += __shfl_xor_sync(0xffffffffu, sdot, 1);                               \
    sdot += __shfl_xor_sync(0xffffffffu, sdot, 2);                               \
    if (y == 0) eagm[((P) ^ 1) * KTAG + j] = sdot * rc;                          \
    { float yk = lgv - Nc;                          /* Kahan N += lgv */         \
      float tk = N + yk;                                                         \
      Nc = (tk - N) - yk;                                                        \
      N = tk; }                                                                  \
  }

__global__ __launch_bounds__(NTHREADS, 2)
void crf_fwd_kernel(const float* __restrict__ scores,
                    const int* __restrict__ targets,
                    const int* __restrict__ lengths,
                    float* __restrict__ out)
{
    extern __shared__ float sdyn[];
    float* buf   = sdyn;                          // NBUF * TILE_F
    float* eagm  = buf + NBUF * TILE_F;           // 2 * KTAG
    int*   tgt_s = (int*)(eagm + 2 * KTAG);       // TLEN

    const int bid = blockIdx.x;
    // pair batch s with 255-s (lengths sorted desc) for per-SM balance
    const int b = (bid < 148) ? bid : (403 - bid);

    const int tid = threadIdx.x;
    const int j   = tid >> 2;            // column 0..47
    const int y   = tid & 3;             // row-group 0..3 (rows y+4m)
    const int len = lengths[b];

    const float* base = scores + (size_t)b * TLEN * KK;

    for (int t = tid; t < len; t += NTHREADS) {
        int tg = targets[b * TLEN + t];
        tgt_s[t] = (tg / KTAG) * PAD + (tg % KTAG);
    }

    // cp.async: exactly 3 chunks per thread (576 = 3*192)
    const uint32_t sbase = (uint32_t)__cvta_generic_to_shared(buf);
    const int c0 = tid, c1 = tid + NTHREADS, c2 = tid + 2 * NTHREADS;
    const uint32_t d0 = (uint32_t)((c0 / CPR) * (PAD * 4) + (c0 % CPR) * 16);
    const uint32_t d1 = (uint32_t)((c1 / CPR) * (PAD * 4) + (c1 % CPR) * 16);
    const uint32_t d2 = (uint32_t)((c2 / CPR) * (PAD * 4) + (c2 % CPR) * 16);
    const uint32_t s0 = (uint32_t)c0 * 16, s1 = (uint32_t)c1 * 16, s2 = (uint32_t)c2 * 16;
    const int ro = y * PAD + j;          // rows y+4m at +m*4*PAD

    // prologue: prime tiles 0..6 into slots 0..6 (7 commits)
    #pragma unroll
    for (int k = 0; k < 7; ++k) {
        if (k < len) {
            const char* s = (const char*)(base + (size_t)k * KK);
            uint32_t d = sbase + (uint32_t)k * (TILE_F * 4);
            cp16(d + d0, s + s0); cp16(d + d1, s + s1); cp16(d + d2, s + s2);
        }
        cp_commit();
    }
    cp_wait<5>();            // tiles 0,1 complete
    __syncthreads();         // published

    // eag_1 at parity 1
    if (y == 0)
        eagm[KTAG + j] = fast_ex2(buf[START_TAG * PAD + j] * L2E);

    float esc[NM];
    if (len > 1) {
        const float* rp = buf + 1 * TILE_F + ro;       // tile 1
        #pragma unroll
        for (int m = 0; m < NM; ++m) esc[m] = fast_ex2(rp[m * 4 * PAD] * L2E);
    }
    float true_sum = (tid == 0) ? buf[tgt_s[0]] : 0.0f;
    float tc = 0.0f, N = 0.0f, Nc = 0.0f;
    const char* srcp = (const char*)(base + (size_t)7 * KK);   // tile 7 = (t=1)+6

    int t = 1;
    for (; t + 7 < len; t += 8) {        // t ≡ 1 (mod 8): compile-time slots
        STEP(t,     1, 1, 2, 7)
        STEP(t + 1, 0, 2, 3, 0)
        STEP(t + 2, 1, 3, 4, 1)
        STEP(t + 3, 0, 4, 5, 2)
        STEP(t + 4, 1, 5, 6, 3)
        STEP(t + 5, 0, 6, 7, 4)
        STEP(t + 6, 1, 7, 0, 5)
        STEP(t + 7, 0, 0, 1, 6)
    }
    for (; t < len; ++t) {               // remainder (<=7): runtime slots
        STEP(t, (t & 1), (t & 7), ((t + 1) & 7), ((t + 6) & 7))
    }

    __syncthreads();
    if (tid == 0)
        g_partial[b] = (fast_lg2(eagm[(len & 1) * KTAG + END_TAG]) + N) * LN2 - true_sum;

    // last-arriving CTA reduces (deterministic fixed-order tree)
    if (tid < 32) {
        unsigned done = 0;
        if (tid == 0) {
            __threadfence();
            done = atomicAdd(&g_count, 1u);
        }
        done = __shfl_sync(0xffffffffu, done, 0);
        if (done == BSZ - 1) {
            __threadfence();
            const volatile float* gp = g_partial;
            float s = 0.0f;
            #pragma unroll
            for (int k = 0; k < BSZ / 32; ++k) s += gp[tid + 32 * k];
            s += __shfl_xor_sync(0xffffffffu, s, 16);
            s += __shfl_xor_sync(0xffffffffu, s, 8);
            s += __shfl_xor_sync(0xffffffffu, s, 4);
            s += __shfl_xor_sync(0xffffffffu, s, 2);
            s += __shfl_xor_sync(0xffffffffu, s, 1);
            if (tid == 0) {
                out[0] = s / (float)BSZ;
                g_count = 0;             // reset for next graph replay
            }
        }
    }
}

extern "C" void kernel_launch(void* const* d_in, const int* in_sizes, int n_in,
                              void* d_out, int out_size)
{
    const float* scores  = (const float*)d_in[0];
    const int*   targets = (const int*)d_in[1];
    const int*   lengths = (const int*)d_in[2];
    float* out = (float*)d_out;

    const int smem_bytes = (NBUF * TILE_F + 2 * KTAG) * 4 + TLEN * 4;  // ~110.4 KB
    cudaFuncSetAttribute(crf_fwd_kernel,
                         cudaFuncAttributeMaxDynamicSharedMemorySize, smem_bytes);

    crf_fwd_kernel<<<BSZ, NTHREADS, smem_bytes>>>(scores, targets, lengths, out);
}

// round 15
// speedup vs baseline: 1.4024x; 1.0471x over previous
#include <cuda_runtime.h>
#include <cstdint>

#define BSZ 256
#define TLEN 512
#define KTAG 48
#define KK 2304                 // floats per (b,t) tile
#define PAD 72                  // padded row stride; (8y+j) bank map -> conflict-free
#define TILE_F (KTAG*PAD)       // 3456 floats per padded tile
#define START_TAG 46
#define END_TAG 47
#define NTHREADS 192
#define NM 12                   // rows per thread: y + 4m, m = 0..11
#define NBUF 8
#define CPR 12                  // 16B chunks per tile row (48 floats = 192B)
#define L2E 1.44269504088896f
#define LN2 0.6931471805599453f

__device__ float g_partial[BSZ];
__device__ unsigned int g_count;   // zero-init; reset by reducing CTA

__device__ __forceinline__ void cp16(uint32_t dst_smem, const void* src) {
    asm volatile("cp.async.cg.shared.global [%0], [%1], 16;" :: "r"(dst_smem), "l"(src));
}
__device__ __forceinline__ void cp_commit() {
    asm volatile("cp.async.commit_group;" ::: "memory");
}
template<int N>
__device__ __forceinline__ void cp_wait() {
    asm volatile("cp.async.wait_group %0;" :: "n"(N) : "memory");
}
__device__ __forceinline__ float fast_ex2(float x) {
    float r; asm("ex2.approx.ftz.f32 %0, %1;" : "=f"(r) : "f"(x)); return r;
}
__device__ __forceinline__ float fast_lg2(float x) {
    float r; asm("lg2.approx.ftz.f32 %0, %1;" : "=f"(r) : "f"(x)); return r;
}
__device__ __forceinline__ float fast_rcp(float x) {
    float r; asm("rcp.approx.ftz.f32 %0, %1;" : "=f"(r) : "f"(x)); return r;
}

// One step for tile T. P = T&1; SCUR=T&7, SNXT=(T+1)&7, SPRE=(T+7)&7.
// srcp -> tile T+7 on entry (prologue loaded 0..7). cp_wait<6> leaves
// tiles T+2..T+7 pending => tile T+1 complete before the esc refill.
// Ring safety: write slot (T+7)&7 = (T-1)&7; tile T-1's last reads were in
// STEP(T-1), before this step's barrier; the write is issued after it.
#define STEP(T, P, SCUR, SNXT, SPRE)                                             \
  {                                                                              \
    __syncthreads();                                /* eag_T published */        \
    const float* eg = eagm + (P) * KTAG;                                         \
    const float e0v = eg[0];                                                     \
    const float rc  = fast_rcp(e0v);                                             \
    const float lgv = fast_lg2(e0v);                                             \
    float a0 = esc[0] * eg[y +  0], a1 = esc[1] * eg[y +  4];                    \
    float a2 = esc[2] * eg[y +  8], a3 = esc[3] * eg[y + 12];                    \
    a0 = fmaf(esc[4],  eg[y + 16], a0); a1 = fmaf(esc[5],  eg[y + 20], a1);      \
    a2 = fmaf(esc[6],  eg[y + 24], a2); a3 = fmaf(esc[7],  eg[y + 28], a3);      \
    a0 = fmaf(esc[8],  eg[y + 32], a0); a1 = fmaf(esc[9],  eg[y + 36], a1);      \
    a2 = fmaf(esc[10], eg[y + 40], a2); a3 = fmaf(esc[11], eg[y + 44], a3);      \
    float sdot = (a0 + a1) + (a2 + a3);                                          \
    if ((T) + 7 < len) {                            /* prefetch tile T+7 */      \
      uint32_t d = sbase + (uint32_t)(SPRE) * (TILE_F * 4);                      \
      cp16(d + d0, srcp + s0); cp16(d + d1, srcp + s1); cp16(d + d2, srcp + s2); \
    }                                                                            \
    srcp += KK * 4;                                                              \
    cp_commit();                                                                 \
    cp_wait<6>();                                   /* tiles <= T+1 complete */  \
    if ((T) + 1 < len) {                            /* esc <- exps(tile T+1) */  \
      const float* rp = buf + (SNXT) * TILE_F + ro;                              \
      _Pragma("unroll")                                                          \
      for (int m = 0; m < NM; ++m) esc[m] = fast_ex2(rp[m * 4 * PAD] * L2E);     \
    }                                                                            \
    if (tid == 0) {                                 /* Kahan true_sum += */      \
      float yk = buf[(SCUR) * TILE_F + tgt_s[T]] - tc;                           \
      float tk = true_sum + yk;                                                  \
      tc = (tk - true_sum) - yk;                                                 \
      true_sum = tk;                                                             \
    }                                                                            \
    sdot += __shfl_xor_sync(0xffffffffu, sdot, 1);                               \
    sdot += __shfl_xor_sync(0xffffffffu, sdot, 2);                               \
    if (y == 0) eagm[((P) ^ 1) * KTAG + j] = sdot * rc;                          \
    { float yk = lgv - Nc;                          /* Kahan N += lgv */         \
      float tk = N + yk;                                                         \
      Nc = (tk - N) - yk;                                                        \
      N = tk; }                                                                  \
  }

__global__ __launch_bounds__(NTHREADS, 2)
void crf_fwd_kernel(const float* __restrict__ scores,
                    const int* __restrict__ targets,
                    const int* __restrict__ lengths,
                    float* __restrict__ out)
{
    extern __shared__ float sdyn[];
    float* buf   = sdyn;                          // NBUF * TILE_F
    float* eagm  = buf + NBUF * TILE_F;           // 2 * KTAG
    int*   tgt_s = (int*)(eagm + 2 * KTAG);       // TLEN

    const int bid = blockIdx.x;
    // pair batch s with 255-s (lengths sorted desc) for per-SM balance
    const int b = (bid < 148) ? bid : (403 - bid);

    const int tid = threadIdx.x;
    const int j   = tid >> 2;            // column 0..47
    const int y   = tid & 3;             // row-group 0..3 (rows y+4m)
    const int len = lengths[b];

    const float* base = scores + (size_t)b * TLEN * KK;

    for (int t = tid; t < len; t += NTHREADS) {
        int tg = targets[b * TLEN + t];
        tgt_s[t] = (tg / KTAG) * PAD + (tg % KTAG);
    }

    // cp.async: exactly 3 chunks per thread (576 = 3*192)
    const uint32_t sbase = (uint32_t)__cvta_generic_to_shared(buf);
    const int c0 = tid, c1 = tid + NTHREADS, c2 = tid + 2 * NTHREADS;
    const uint32_t d0 = (uint32_t)((c0 / CPR) * (PAD * 4) + (c0 % CPR) * 16);
    const uint32_t d1 = (uint32_t)((c1 / CPR) * (PAD * 4) + (c1 % CPR) * 16);
    const uint32_t d2 = (uint32_t)((c2 / CPR) * (PAD * 4) + (c2 % CPR) * 16);
    const uint32_t s0 = (uint32_t)c0 * 16, s1 = (uint32_t)c1 * 16, s2 = (uint32_t)c2 * 16;
    const int ro = y * PAD + j;          // rows y+4m at +m*4*PAD

    // prologue: prime tiles 0..7 into slots 0..7 (8 commits)
    #pragma unroll
    for (int k = 0; k < 8; ++k) {
        if (k < len) {
            const char* s = (const char*)(base + (size_t)k * KK);
            uint32_t d = sbase + (uint32_t)k * (TILE_F * 4);
            cp16(d + d0, s + s0); cp16(d + d1, s + s1); cp16(d + d2, s + s2);
        }
        cp_commit();
    }
    cp_wait<6>();            // tiles 0,1 complete
    __syncthreads();         // published

    // eag_1 at parity 1
    if (y == 0)
        eagm[KTAG + j] = fast_ex2(buf[START_TAG * PAD + j] * L2E);

    float esc[NM];
    if (len > 1) {
        const float* rp = buf + 1 * TILE_F + ro;       // tile 1
        #pragma unroll
        for (int m = 0; m < NM; ++m) esc[m] = fast_ex2(rp[m * 4 * PAD] * L2E);
    }
    float true_sum = (tid == 0) ? buf[tgt_s[0]] : 0.0f;
    float tc = 0.0f, N = 0.0f, Nc = 0.0f;
    const char* srcp = (const char*)(base + (size_t)8 * KK);   // tile 8 = (t=1)+7

    int t = 1;
    for (; t + 7 < len; t += 8) {        // t ≡ 1 (mod 8): compile-time slots
        STEP(t,     1, 1, 2, 0)
        STEP(t + 1, 0, 2, 3, 1)
        STEP(t + 2, 1, 3, 4, 2)
        STEP(t + 3, 0, 4, 5, 3)
        STEP(t + 4, 1, 5, 6, 4)
        STEP(t + 5, 0, 6, 7, 5)
        STEP(t + 6, 1, 7, 0, 6)
        STEP(t + 7, 0, 0, 1, 7)
    }
    for (; t < len; ++t) {               // remainder (<=7): runtime slots
        STEP(t, (t & 1), (t & 7), ((t + 1) & 7), ((t + 7) & 7))
    }

    __syncthreads();
    if (tid == 0)
        g_partial[b] = (fast_lg2(eagm[(len & 1) * KTAG + END_TAG]) + N) * LN2 - true_sum;

    // last-arriving CTA reduces (deterministic fixed-order tree)
    if (tid < 32) {
        unsigned done = 0;
        if (tid == 0) {
            __threadfence();
            done = atomicAdd(&g_count, 1u);
        }
        done = __shfl_sync(0xffffffffu, done, 0);
        if (done == BSZ - 1) {
            __threadfence();
            const volatile float* gp = g_partial;
            float s = 0.0f;
            #pragma unroll
            for (int k = 0; k < BSZ / 32; ++k) s += gp[tid + 32 * k];
            s += __shfl_xor_sync(0xffffffffu, s, 16);
            s += __shfl_xor_sync(0xffffffffu, s, 8);
            s += __shfl_xor_sync(0xffffffffu, s, 4);
            s += __shfl_xor_sync(0xffffffffu, s, 2);
            s += __shfl_xor_sync(0xffffffffu, s, 1);
            if (tid == 0) {
                out[0] = s / (float)BSZ;
                g_count = 0;             // reset for next graph replay
            }
        }
    }
}

extern "C" void kernel_launch(void* const* d_in, const int* in_sizes, int n_in,
                              void* d_out, int out_size)
{
    const float* scores  = (const float*)d_in[0];
    const int*   targets = (const int*)d_in[1];
    const int*   lengths = (const int*)d_in[2];
    float* out = (float*)d_out;

    const int smem_bytes = (NBUF * TILE_F + 2 * KTAG) * 4 + TLEN * 4;  // ~110.4 KB
    cudaFuncSetAttribute(crf_fwd_kernel,
                         cudaFuncAttributeMaxDynamicSharedMemorySize, smem_bytes);

    crf_fwd_kernel<<<BSZ, NTHREADS, smem_bytes>>>(scores, targets, lengths, out);
}

// round 16
// speedup vs baseline: 1.4334x; 1.0221x over previous
#include <cuda_runtime.h>
#include <cstdint>

#define BSZ 256
#define TLEN 512
#define KTAG 48
#define KK 2304                 // floats per (b,t) tile
#define PAD 72                  // padded row stride; (8y+j) bank map -> conflict-free
#define TILE_F (KTAG*PAD)       // 3456 floats per padded tile
#define START_TAG 46
#define END_TAG 47
#define NTHREADS 192
#define NM 12                   // rows per thread: y + 4m, m = 0..11
#define NBUF 8
#define CPR 12                  // 16B chunks per tile row (48 floats = 192B)
#define PFD 12                  // L2 prefetch distance (tiles); window ~3us -> L2-resident
#define LONG_LEN 384            // only the ~64 longest chains get priority
#define L2E 1.44269504088896f
#define LN2 0.6931471805599453f

__device__ float g_partial[BSZ];
__device__ unsigned int g_count;   // zero-init; reset by reducing CTA

__device__ __forceinline__ void cp16(uint32_t dst_smem, const void* src) {
    asm volatile("cp.async.cg.shared.global [%0], [%1], 16;" :: "r"(dst_smem), "l"(src));
}
__device__ __forceinline__ void cp_commit() {
    asm volatile("cp.async.commit_group;" ::: "memory");
}
template<int N>
__device__ __forceinline__ void cp_wait() {
    asm volatile("cp.async.wait_group %0;" :: "n"(N) : "memory");
}
__device__ __forceinline__ void l2_prefetch(const void* p) {
    asm volatile("prefetch.global.L2 [%0];" :: "l"(p));
}
__device__ __forceinline__ float fast_ex2(float x) {
    float r; asm("ex2.approx.ftz.f32 %0, %1;" : "=f"(r) : "f"(x)); return r;
}
__device__ __forceinline__ float fast_lg2(float x) {
    float r; asm("lg2.approx.ftz.f32 %0, %1;" : "=f"(r) : "f"(x)); return r;
}
__device__ __forceinline__ float fast_rcp(float x) {
    float r; asm("rcp.approx.ftz.f32 %0, %1;" : "=f"(r) : "f"(x)); return r;
}

// One step for tile T. P = T&1; SCUR=T&7, SNXT=(T+1)&7, SPRE=(T+7)&7.
// srcp -> tile T+7 on entry. cp_wait<6> completes tiles <= T+1.
// pfp -> this thread's 128B line of tile T+PFD (long chains, tid<72).
#define STEP(T, P, SCUR, SNXT, SPRE)                                             \
  {                                                                              \
    __syncthreads();                                /* eag_T published */        \
    const float* eg = eagm + (P) * KTAG;                                         \
    const float e0v = eg[0];                                                     \
    const float rc  = fast_rcp(e0v);                                             \
    const float lgv = fast_lg2(e0v);                                             \
    float a0 = esc[0] * eg[y +  0], a1 = esc[1] * eg[y +  4];                    \
    float a2 = esc[2] * eg[y +  8], a3 = esc[3] * eg[y + 12];                    \
    a0 = fmaf(esc[4],  eg[y + 16], a0); a1 = fmaf(esc[5],  eg[y + 20], a1);      \
    a2 = fmaf(esc[6],  eg[y + 24], a2); a3 = fmaf(esc[7],  eg[y + 28], a3);      \
    a0 = fmaf(esc[8],  eg[y + 32], a0); a1 = fmaf(esc[9],  eg[y + 36], a1);      \
    a2 = fmaf(esc[10], eg[y + 40], a2); a3 = fmaf(esc[11], eg[y + 44], a3);      \
    float sdot = (a0 + a1) + (a2 + a3);                                          \
    if ((T) + 7 < len) {                            /* prefetch tile T+7 */      \
      uint32_t d = sbase + (uint32_t)(SPRE) * (TILE_F * 4);                      \
      cp16(d + d0, srcp + s0); cp16(d + d1, srcp + s1); cp16(d + d2, srcp + s2); \
    }                                                                            \
    srcp += KK * 4;                                                              \
    if (longp && (T) + PFD < len) l2_prefetch(pfp); /* short-window L2 stage */  \
    pfp += KK * 4;                                                               \
    cp_commit();                                                                 \
    cp_wait<6>();                                   /* tiles <= T+1 complete */  \
    if ((T) + 1 < len) {                            /* esc <- exps(tile T+1) */  \
      const float* rp = buf + (SNXT) * TILE_F + ro;                              \
      _Pragma("unroll")                                                          \
      for (int m = 0; m < NM; ++m) esc[m] = fast_ex2(rp[m * 4 * PAD] * L2E);     \
    }                                                                            \
    if (tid == 0) {                                 /* Kahan true_sum += */      \
      float yk = buf[(SCUR) * TILE_F + tgt_s[T]] - tc;                           \
      float tk = true_sum + yk;                                                  \
      tc = (tk - true_sum) - yk;                                                 \
      true_sum = tk;                                                             \
    }                                                                            \
    sdot += __shfl_xor_sync(0xffffffffu, sdot, 1);                               \
    sdot += __shfl_xor_sync(0xffffffffu, sdot, 2);                               \
    if (y == 0) eagm[((P) ^ 1) * KTAG + j] = sdot * rc;                          \
    { float yk = lgv - Nc;                          /* Kahan N += lgv */         \
      float tk = N + yk;                                                         \
      Nc = (tk - N) - yk;                                                        \
      N = tk; }                                                                  \
  }

__global__ __launch_bounds__(NTHREADS, 2)
void crf_fwd_kernel(const float* __restrict__ scores,
                    const int* __restrict__ targets,
                    const int* __restrict__ lengths,
                    float* __restrict__ out)
{
    extern __shared__ float sdyn[];
    float* buf   = sdyn;                          // NBUF * TILE_F
    float* eagm  = buf + NBUF * TILE_F;           // 2 * KTAG
    int*   tgt_s = (int*)(eagm + 2 * KTAG);       // TLEN

    const int bid = blockIdx.x;
    // pair batch s with 255-s (lengths sorted desc) for per-SM balance
    const int b = (bid < 148) ? bid : (403 - bid);

    const int tid = threadIdx.x;
    const int j   = tid >> 2;            // column 0..47
    const int y   = tid & 3;             // row-group 0..3 (rows y+4m)
    const int len = lengths[b];

    const float* base = scores + (size_t)b * TLEN * KK;

    for (int t = tid; t < len; t += NTHREADS) {
        int tg = targets[b * TLEN + t];
        tgt_s[t] = (tg / KTAG) * PAD + (tg % KTAG);
    }

    // cp.async: exactly 3 chunks per thread (576 = 3*192)
    const uint32_t sbase = (uint32_t)__cvta_generic_to_shared(buf);
    const int c0 = tid, c1 = tid + NTHREADS, c2 = tid + 2 * NTHREADS;
    const uint32_t d0 = (uint32_t)((c0 / CPR) * (PAD * 4) + (c0 % CPR) * 16);
    const uint32_t d1 = (uint32_t)((c1 / CPR) * (PAD * 4) + (c1 % CPR) * 16);
    const uint32_t d2 = (uint32_t)((c2 / CPR) * (PAD * 4) + (c2 % CPR) * 16);
    const uint32_t s0 = (uint32_t)c0 * 16, s1 = (uint32_t)c1 * 16, s2 = (uint32_t)c2 * 16;
    const int ro = y * PAD + j;          // rows y+4m at +m*4*PAD

    // L2 priority prefetch: 72 threads cover one 9216B tile in 128B lines
    const bool longp = (tid < 72) && (len >= LONG_LEN);
    const char* pfp = (const char*)base + (size_t)(1 + PFD) * (KK * 4) + tid * 128;

    // prologue: prime tiles 0..7 into slots 0..7 (8 commits)
    #pragma unroll
    for (int k = 0; k < 8; ++k) {
        if (k < len) {
            const char* s = (const char*)(base + (size_t)k * KK);
            uint32_t d = sbase + (uint32_t)k * (TILE_F * 4);
            cp16(d + d0, s + s0); cp16(d + d1, s + s1); cp16(d + d2, s + s2);
        }
        cp_commit();
    }
    cp_wait<6>();            // tiles 0,1 complete
    __syncthreads();         // published

    // eag_1 at parity 1
    if (y == 0)
        eagm[KTAG + j] = fast_ex2(buf[START_TAG * PAD + j] * L2E);

    float esc[NM];
    if (len > 1) {
        const float* rp = buf + 1 * TILE_F + ro;       // tile 1
        #pragma unroll
        for (int m = 0; m < NM; ++m) esc[m] = fast_ex2(rp[m * 4 * PAD] * L2E);
    }
    float true_sum = (tid == 0) ? buf[tgt_s[0]] : 0.0f;
    float tc = 0.0f, N = 0.0f, Nc = 0.0f;
    const char* srcp = (const char*)(base + (size_t)8 * KK);   // tile 8 = (t=1)+7

    int t = 1;
    for (; t + 7 < len; t += 8) {        // t ≡ 1 (mod 8): compile-time slots
        STEP(t,     1, 1, 2, 0)
        STEP(t + 1, 0, 2, 3, 1)
        STEP(t + 2, 1, 3, 4, 2)
        STEP(t + 3, 0, 4, 5, 3)
        STEP(t + 4, 1, 5, 6, 4)
        STEP(t + 5, 0, 6, 7, 5)
        STEP(t + 6, 1, 7, 0, 6)
        STEP(t + 7, 0, 0, 1, 7)
    }
    for (; t < len; ++t) {               // remainder (<=7): runtime slots
        STEP(t, (t & 1), (t & 7), ((t + 1) & 7), ((t + 7) & 7))
    }

    __syncthreads();
    if (tid == 0)
        g_partial[b] = (fast_lg2(eagm[(len & 1) * KTAG + END_TAG]) + N) * LN2 - true_sum;

    // last-arriving CTA reduces (deterministic fixed-order tree)
    if (tid < 32) {
        unsigned done = 0;
        if (tid == 0) {
            __threadfence();
            done = atomicAdd(&g_count, 1u);
        }
        done = __shfl_sync(0xffffffffu, done, 0);
        if (done == BSZ - 1) {
            __threadfence();
            const volatile float* gp = g_partial;
            float s = 0.0f;
            #pragma unroll
            for (int k = 0; k < BSZ / 32; ++k) s += gp[tid + 32 * k];
            s += __shfl_xor_sync(0xffffffffu, s, 16);
            s += __shfl_xor_sync(0xffffffffu, s, 8);
            s += __shfl_xor_sync(0xffffffffu, s, 4);
            s += __shfl_xor_sync(0xffffffffu, s, 2);
            s += __shfl_xor_sync(0xffffffffu, s, 1);
            if (tid == 0) {
                out[0] = s / (float)BSZ;
                g_count = 0;             // reset for next graph replay
            }
        }
    }
}

extern "C" void kernel_launch(void* const* d_in, const int* in_sizes, int n_in,
                              void* d_out, int out_size)
{
    const float* scores  = (const float*)d_in[0];
    const int*   targets = (const int*)d_in[1];
    const int*   lengths = (const int*)d_in[2];
    float* out = (float*)d_out;

    const int smem_bytes = (NBUF * TILE_F + 2 * KTAG) * 4 + TLEN * 4;  // ~110.4 KB
    cudaFuncSetAttribute(crf_fwd_kernel,
                         cudaFuncAttributeMaxDynamicSharedMemorySize, smem_bytes);

    crf_fwd_kernel<<<BSZ, NTHREADS, smem_bytes>>>(scores, targets, lengths, out);
}

// round 17
// speedup vs baseline: 1.4375x; 1.0028x over previous
#include <cuda_runtime.h>
#include <cstdint>

#define BSZ 256
#define TLEN 512
#define KTAG 48
#define KK 2304                 // floats per (b,t) tile
#define PAD 72                  // padded row stride; (8y+j) bank map -> conflict-free
#define TILE_F (KTAG*PAD)       // 3456 floats per padded tile
#define START_TAG 46
#define END_TAG 47
#define NTHREADS 192
#define NM 12                   // rows per thread: y + 4m, m = 0..11
#define NBUF 8
#define CPR 12                  // 16B chunks per tile row (48 floats = 192B)
#define PFD 24                  // L2 prefetch distance (tiles); ~18MB staged, L2-resident
#define LONG_LEN 352            // ~80 longest chains get DRAM-share priority
#define L2E 1.44269504088896f
#define LN2 0.6931471805599453f

__device__ float g_partial[BSZ];
__device__ unsigned int g_count;   // zero-init; reset by reducing CTA

__device__ __forceinline__ void cp16(uint32_t dst_smem, const void* src) {
    asm volatile("cp.async.cg.shared.global [%0], [%1], 16;" :: "r"(dst_smem), "l"(src));
}
__device__ __forceinline__ void cp_commit() {
    asm volatile("cp.async.commit_group;" ::: "memory");
}
template<int N>
__device__ __forceinline__ void cp_wait() {
    asm volatile("cp.async.wait_group %0;" :: "n"(N) : "memory");
}
__device__ __forceinline__ void l2_prefetch(const void* p) {
    asm volatile("prefetch.global.L2 [%0];" :: "l"(p));
}
__device__ __forceinline__ float fast_ex2(float x) {
    float r; asm("ex2.approx.ftz.f32 %0, %1;" : "=f"(r) : "f"(x)); return r;
}
__device__ __forceinline__ float fast_lg2(float x) {
    float r; asm("lg2.approx.ftz.f32 %0, %1;" : "=f"(r) : "f"(x)); return r;
}
__device__ __forceinline__ float fast_rcp(float x) {
    float r; asm("rcp.approx.ftz.f32 %0, %1;" : "=f"(r) : "f"(x)); return r;
}

// One step for tile T. P = T&1; SCUR=T&7, SNXT=(T+1)&7, SPRE=(T+7)&7.
// srcp -> tile T+7 on entry. cp_wait<6> completes tiles <= T+1.
// pfp -> this thread's 128B line of tile T+PFD (long chains, tid<72).
#define STEP(T, P, SCUR, SNXT, SPRE)                                             \
  {                                                                              \
    __syncthreads();                                /* eag_T published */        \
    const float* eg = eagm + (P) * KTAG;                                         \
    const float e0v = eg[0];                                                     \
    const float rc  = fast_rcp(e0v);                                             \
    const float lgv = fast_lg2(e0v);                                             \
    float a0 = esc[0] * eg[y +  0], a1 = esc[1] * eg[y +  4];                    \
    float a2 = esc[2] * eg[y +  8], a3 = esc[3] * eg[y + 12];                    \
    a0 = fmaf(esc[4],  eg[y + 16], a0); a1 = fmaf(esc[5],  eg[y + 20], a1);      \
    a2 = fmaf(esc[6],  eg[y + 24], a2); a3 = fmaf(esc[7],  eg[y + 28], a3);      \
    a0 = fmaf(esc[8],  eg[y + 32], a0); a1 = fmaf(esc[9],  eg[y + 36], a1);      \
    a2 = fmaf(esc[10], eg[y + 40], a2); a3 = fmaf(esc[11], eg[y + 44], a3);      \
    float sdot = (a0 + a1) + (a2 + a3);                                          \
    if ((T) + 7 < len) {                            /* prefetch tile T+7 */      \
      uint32_t d = sbase + (uint32_t)(SPRE) * (TILE_F * 4);                      \
      cp16(d + d0, srcp + s0); cp16(d + d1, srcp + s1); cp16(d + d2, srcp + s2); \
    }                                                                            \
    srcp += KK * 4;                                                              \
    if (longp && (T) + PFD < len) l2_prefetch(pfp); /* L2-resident window */     \
    pfp += KK * 4;                                                               \
    cp_commit();                                                                 \
    cp_wait<6>();                                   /* tiles <= T+1 complete */  \
    if ((T) + 1 < len) {                            /* esc <- exps(tile T+1) */  \
      const float* rp = buf + (SNXT) * TILE_F + ro;                              \
      _Pragma("unroll")                                                          \
      for (int m = 0; m < NM; ++m) esc[m] = fast_ex2(rp[m * 4 * PAD] * L2E);     \
    }                                                                            \
    if (tid == 0) {                                 /* Kahan true_sum += */      \
      float yk = buf[(SCUR) * TILE_F + tgt_s[T]] - tc;                           \
      float tk = true_sum + yk;                                                  \
      tc = (tk - true_sum) - yk;                                                 \
      true_sum = tk;                                                             \
    }                                                                            \
    sdot += __shfl_xor_sync(0xffffffffu, sdot, 1);                               \
    sdot += __shfl_xor_sync(0xffffffffu, sdot, 2);                               \
    if (y == 0) eagm[((P) ^ 1) * KTAG + j] = sdot * rc;                          \
    { float yk = lgv - Nc;                          /* Kahan N += lgv */         \
      float tk = N + yk;                                                         \
      Nc = (tk - N) - yk;                                                        \
      N = tk; }                                                                  \
  }

__global__ __launch_bounds__(NTHREADS, 2)
void crf_fwd_kernel(const float* __restrict__ scores,
                    const int* __restrict__ targets,
                    const int* __restrict__ lengths,
                    float* __restrict__ out)
{
    extern __shared__ float sdyn[];
    float* buf   = sdyn;                          // NBUF * TILE_F
    float* eagm  = buf + NBUF * TILE_F;           // 2 * KTAG
    int*   tgt_s = (int*)(eagm + 2 * KTAG);       // TLEN

    const int bid = blockIdx.x;
    // pair batch s with 255-s (lengths sorted desc) for per-SM balance
    const int b = (bid < 148) ? bid : (403 - bid);

    const int tid = threadIdx.x;
    const int j   = tid >> 2;            // column 0..47
    const int y   = tid & 3;             // row-group 0..3 (rows y+4m)
    const int len = lengths[b];

    const float* base = scores + (size_t)b * TLEN * KK;

    for (int t = tid; t < len; t += NTHREADS) {
        int tg = targets[b * TLEN + t];
        tgt_s[t] = (tg / KTAG) * PAD + (tg % KTAG);
    }

    // cp.async: exactly 3 chunks per thread (576 = 3*192)
    const uint32_t sbase = (uint32_t)__cvta_generic_to_shared(buf);
    const int c0 = tid, c1 = tid + NTHREADS, c2 = tid + 2 * NTHREADS;
    const uint32_t d0 = (uint32_t)((c0 / CPR) * (PAD * 4) + (c0 % CPR) * 16);
    const uint32_t d1 = (uint32_t)((c1 / CPR) * (PAD * 4) + (c1 % CPR) * 16);
    const uint32_t d2 = (uint32_t)((c2 / CPR) * (PAD * 4) + (c2 % CPR) * 16);
    const uint32_t s0 = (uint32_t)c0 * 16, s1 = (uint32_t)c1 * 16, s2 = (uint32_t)c2 * 16;
    const int ro = y * PAD + j;          // rows y+4m at +m*4*PAD

    // L2 priority prefetch: 72 threads cover one 9216B tile in 128B lines
    const bool longp = (tid < 72) && (len >= LONG_LEN);
    const char* pfp = (const char*)base + (size_t)(1 + PFD) * (KK * 4) + tid * 128;

    // prologue: prime tiles 0..7 into slots 0..7 (8 commits)
    #pragma unroll
    for (int k = 0; k < 8; ++k) {
        if (k < len) {
            const char* s = (const char*)(base + (size_t)k * KK);
            uint32_t d = sbase + (uint32_t)k * (TILE_F * 4);
            cp16(d + d0, s + s0); cp16(d + d1, s + s1); cp16(d + d2, s + s2);
        }
        cp_commit();
    }
    cp_wait<6>();            // tiles 0,1 complete
    __syncthreads();         // published

    // eag_1 at parity 1
    if (y == 0)
        eagm[KTAG + j] = fast_ex2(buf[START_TAG * PAD + j] * L2E);

    float esc[NM];
    if (len > 1) {
        const float* rp = buf + 1 * TILE_F + ro;       // tile 1
        #pragma unroll
        for (int m = 0; m < NM; ++m) esc[m] = fast_ex2(rp[m * 4 * PAD] * L2E);
    }
    float true_sum = (tid == 0) ? buf[tgt_s[0]] : 0.0f;
    float tc = 0.0f, N = 0.0f, Nc = 0.0f;
    const char* srcp = (const char*)(base + (size_t)8 * KK);   // tile 8 = (t=1)+7

    int t = 1;
    for (; t + 7 < len; t += 8) {        // t ≡ 1 (mod 8): compile-time slots
        STEP(t,     1, 1, 2, 0)
        STEP(t + 1, 0, 2, 3, 1)
        STEP(t + 2, 1, 3, 4, 2)
        STEP(t + 3, 0, 4, 5, 3)
        STEP(t + 4, 1, 5, 6, 4)
        STEP(t + 5, 0, 6, 7, 5)
        STEP(t + 6, 1, 7, 0, 6)
        STEP(t + 7, 0, 0, 1, 7)
    }
    for (; t < len; ++t) {               // remainder (<=7): runtime slots
        STEP(t, (t & 1), (t & 7), ((t + 1) & 7), ((t + 7) & 7))
    }

    __syncthreads();
    if (tid == 0)
        g_partial[b] = (fast_lg2(eagm[(len & 1) * KTAG + END_TAG]) + N) * LN2 - true_sum;

    // last-arriving CTA reduces (deterministic fixed-order tree)
    if (tid < 32) {
        unsigned done = 0;
        if (tid == 0) {
            __threadfence();
            done = atomicAdd(&g_count, 1u);
        }
        done = __shfl_sync(0xffffffffu, done, 0);
        if (done == BSZ - 1) {
            __threadfence();
            const volatile float* gp = g_partial;
            float s = 0.0f;
            #pragma unroll
            for (int k = 0; k < BSZ / 32; ++k) s += gp[tid + 32 * k];
            s += __shfl_xor_sync(0xffffffffu, s, 16);
            s += __shfl_xor_sync(0xffffffffu, s, 8);
            s += __shfl_xor_sync(0xffffffffu, s, 4);
            s += __shfl_xor_sync(0xffffffffu, s, 2);
            s += __shfl_xor_sync(0xffffffffu, s, 1);
            if (tid == 0) {
                out[0] = s / (float)BSZ;
                g_count = 0;             // reset for next graph replay
            }
        }
    }
}

extern "C" void kernel_launch(void* const* d_in, const int* in_sizes, int n_in,
                              void* d_out, int out_size)
{
    const float* scores  = (const float*)d_in[0];
    const int*   targets = (const int*)d_in[1];
    const int*   lengths = (const int*)d_in[2];
    float* out = (float*)d_out;

    const int smem_bytes = (NBUF * TILE_F + 2 * KTAG) * 4 + TLEN * 4;  // ~110.4 KB
    cudaFuncSetAttribute(crf_fwd_kernel,
                         cudaFuncAttributeMaxDynamicSharedMemorySize, smem_bytes);

    crf_fwd_kernel<<<BSZ, NTHREADS, smem_bytes>>>(scores, targets, lengths, out);
}